// round 15
// baseline (speedup 1.0000x reference)
#include <cuda_runtime.h>
#include <cuda_bf16.h>
#include <cstdint>

// InverseAvgPool1d, K=8 -> half=4, s=9.
// S'[t] = 8*A[t] - 8*x0*[t%9 <= 4],  A[t] = stride-9 prefix sum of x.
// out[t] = S'[t] - S'[t-1]   (S'[-1] = 0).  Correction folded into writeback.
//
// One row per CTA, 256 threads (8 warps): warp w owns chain w; warp 0 also
// owns chain 8 (c += 8 -> each chain exactly once, slot-sets disjoint mod 9).
// 32 regs / 16KB smem => 8 CTAs/SM (2048 threads) for max DRAM overlap.
// Gather/writeback slots are lane-private => no barrier between them.

#define ROW_T 4096
#define NTHREADS 256
#define PER_LANE 15             // 32*15 = 480 slots; real max 456

__global__ __launch_bounds__(NTHREADS, 8)
void inv_avgpool_kernel(const float* __restrict__ x, float* __restrict__ out) {
    __shared__ __align__(16) float s[ROW_T];

    const int tid = threadIdx.x;
    const int lane = tid & 31;
    const int w = tid >> 5;                  // warp 0..7

    const size_t row = blockIdx.x;
    const float4* __restrict__ xr = (const float4*)(x + row * ROW_T);
    float4* __restrict__ outr = (float4*)(out + row * ROW_T);

    // x0 via global broadcast (no smem dependency on s[0])
    const float x0 = __ldg(x + row * ROW_T);

    // 1) coalesced stage, streaming loads (exactly 4 iterations)
    #pragma unroll
    for (int q = tid; q < ROW_T / 4; q += NTHREADS) {
        ((float4*)s)[q] = __ldcs(xr + q);
    }
    __syncthreads();

    // 2) chains: warp w -> chain w; warp 0 additionally -> chain 8.
    //    Chain c's slots are t == c (mod 9): disjoint across c, so the only
    //    warp ever touching chain c's slots is its owner. Chain 8 is gathered
    //    by warp 0 after writing chain 0 — different residue class, safe.
    #pragma unroll 1
    for (int c = w; c < 9; c += 8) {
        const int base = c + 135 * lane;     // lanes 0..29: base+126 <= 4049
        const int lim30 = (c == 0) ? 6 : 5;  // lane 30 valid count

        // gather: lane l accumulates chain slots [15l, 15l+15) (lane-private)
        float a[PER_LANE];
        float run = 0.f;
        if (lane < 30) {
            #pragma unroll
            for (int j = 0; j < PER_LANE; j++) { run += s[base + 9 * j]; a[j] = run; }
        } else if (lane == 30) {
            #pragma unroll
            for (int j = 0; j < PER_LANE; j++) {
                if (j < lim30) run += s[base + 9 * j];
                a[j] = run;
            }
        }

        // warp scan over lane totals -> exclusive carry (warp-synchronous)
        float incl = run;
        #pragma unroll
        for (int off = 1; off < 32; off <<= 1) {
            float up = __shfl_up_sync(0xffffffffu, incl, off);
            if (lane >= off) incl += up;
        }
        float e8 = 8.f * (incl - run);
        if (c <= 4) e8 -= 8.f * x0;          // fold x0 correction into S'

        // writeback S' in place — same lane-private slots, no barrier needed
        if (lane < 30) {
            #pragma unroll
            for (int j = 0; j < PER_LANE; j++) s[base + 9 * j] = fmaf(8.f, a[j], e8);
        } else if (lane == 30) {
            #pragma unroll
            for (int j = 0; j < PER_LANE; j++)
                if (j < lim30) s[base + 9 * j] = fmaf(8.f, a[j], e8);
        }
    }
    __syncthreads();

    // 3) diff pass: out[t] = S'[t] - S'[t-1], evict-first streaming stores
    #pragma unroll
    for (int q = tid; q < ROW_T / 4; q += NTHREADS) {
        float4 B = ((const float4*)s)[q];
        float prevw = __shfl_up_sync(0xffffffffu, B.w, 1);
        if (lane == 0) prevw = (q == 0) ? 0.f : s[4 * q - 1];
        float4 o;
        o.x = B.x - prevw;
        o.y = B.y - B.x;
        o.z = B.z - B.y;
        o.w = B.w - B.z;
        __stcs(outr + q, o);
    }
}

extern "C" void kernel_launch(void* const* d_in, const int* in_sizes, int n_in,
                              void* d_out, int out_size) {
    const float* x = (const float*)d_in[0];
    float* out = (float*)d_out;
    const int rows = in_sizes[0] / ROW_T;   // 16384
    inv_avgpool_kernel<<<rows, NTHREADS>>>(x, out);
}

// round 16
// speedup vs baseline: 1.0102x; 1.0102x over previous
#include <cuda_runtime.h>
#include <cuda_bf16.h>
#include <cstdint>

// InverseAvgPool1d, K=8 -> half=4, s=9.
// S'[t] = 8*A[t] - 8*x0*[t%9 <= 4],  A[t] = stride-9 prefix sum of x.
// out[t] = S'[t] - S'[t-1]   (S'[-1] = 0).  Correction folded into writeback.
//
// Measured optimum (R13): one row per CTA, 9 warps = 9 residue chains
// (perfectly balanced), 31 regs / 16KB smem => 7 CTAs/SM. Gather/writeback
// slots are lane-private => no barrier between gather and writeback.
// Streaming loads + evict-first stores.

#define ROW_T 4096
#define NWARP 9
#define NTHREADS (NWARP * 32)   // 288
#define PER_LANE 15             // 32*15 = 480 slots; real max 456

__global__ __launch_bounds__(NTHREADS, 7)
void inv_avgpool_kernel(const float* __restrict__ x, float* __restrict__ out) {
    __shared__ __align__(16) float s[ROW_T];

    const int tid = threadIdx.x;
    const int lane = tid & 31;
    const int r = tid >> 5;                  // residue chain 0..8

    const size_t row = blockIdx.x;
    const float4* __restrict__ xr = (const float4*)(x + row * ROW_T);
    float4* __restrict__ outr = (float4*)(out + row * ROW_T);

    // x0 via global broadcast (no smem dependency on s[0])
    const float x0 = __ldg(x + row * ROW_T);

    // 1) coalesced stage, streaming loads
    #pragma unroll
    for (int q = tid; q < ROW_T / 4; q += NTHREADS) {
        ((float4*)s)[q] = __ldcs(xr + q);
    }
    __syncthreads();

    const int base = r + 135 * lane;         // lanes 0..29: base+126 <= 4049
    const int lim30 = (r == 0) ? 6 : 5;      // lane 30 valid count

    // 2) gather: lane l accumulates chain slots [15l, 15l+15) (lane-private)
    float a[PER_LANE];
    float run = 0.f;
    if (lane < 30) {
        #pragma unroll
        for (int j = 0; j < PER_LANE; j++) { run += s[base + 9 * j]; a[j] = run; }
    } else if (lane == 30) {
        #pragma unroll
        for (int j = 0; j < PER_LANE; j++) {
            if (j < lim30) run += s[base + 9 * j];
            a[j] = run;
        }
    }

    // 3) warp scan over lane totals -> exclusive carry (warp-synchronous)
    float incl = run;
    #pragma unroll
    for (int off = 1; off < 32; off <<= 1) {
        float up = __shfl_up_sync(0xffffffffu, incl, off);
        if (lane >= off) incl += up;
    }
    float e8 = 8.f * (incl - run);
    if (r <= 4) e8 -= 8.f * x0;              // fold x0 correction into S'

    // 4) writeback S' in place — same lane-private slots, no barrier needed
    if (lane < 30) {
        #pragma unroll
        for (int j = 0; j < PER_LANE; j++) s[base + 9 * j] = fmaf(8.f, a[j], e8);
    } else if (lane == 30) {
        #pragma unroll
        for (int j = 0; j < PER_LANE; j++)
            if (j < lim30) s[base + 9 * j] = fmaf(8.f, a[j], e8);
    }
    __syncthreads();

    // 5) diff pass: out[t] = S'[t] - S'[t-1], evict-first streaming stores
    #pragma unroll
    for (int q = tid; q < ROW_T / 4; q += NTHREADS) {
        float4 B = ((const float4*)s)[q];
        float prevw = __shfl_up_sync(0xffffffffu, B.w, 1);
        if (lane == 0) prevw = (q == 0) ? 0.f : s[4 * q - 1];
        float4 o;
        o.x = B.x - prevw;
        o.y = B.y - B.x;
        o.z = B.z - B.y;
        o.w = B.w - B.z;
        __stcs(outr + q, o);
    }
}

extern "C" void kernel_launch(void* const* d_in, const int* in_sizes, int n_in,
                              void* d_out, int out_size) {
    const float* x = (const float*)d_in[0];
    float* out = (float*)d_out;
    const int rows = in_sizes[0] / ROW_T;   // 16384
    inv_avgpool_kernel<<<rows, NTHREADS>>>(x, out);
}

// round 17
// speedup vs baseline: 1.0146x; 1.0043x over previous
#include <cuda_runtime.h>
#include <cuda_bf16.h>
#include <cstdint>

// InverseAvgPool1d, K=8 -> half=4, s=9.
// S'[t] = 8*A[t] - 8*x0*[t%9 <= 4],  A[t] = stride-9 prefix sum of x.
// out[t] = S'[t] - S'[t-1]   (S'[-1] = 0).  Correction folded into writeback.
//
// Converged optimum (R13): one row per CTA, 9 warps = 9 residue chains
// (perfectly balanced), 31 regs / 16KB smem => 7 CTAs/SM. Gather/writeback
// slots are lane-private => no barrier between gather and writeback.
// Streaming loads + evict-first stores. Measured 6.24 TB/s (~90% of the
// chip's mixed-stream LTS ceiling); all structural alternatives measured
// slower (TMA stage, cp.async pipelines, persistence, 96/256-thread CTAs,
// 2-row CTAs, write-through stores).

#define ROW_T 4096
#define NWARP 9
#define NTHREADS (NWARP * 32)   // 288
#define PER_LANE 15             // 32*15 = 480 slots; real max 456

__global__ __launch_bounds__(NTHREADS, 7)
void inv_avgpool_kernel(const float* __restrict__ x, float* __restrict__ out) {
    __shared__ __align__(16) float s[ROW_T];

    const int tid = threadIdx.x;
    const int lane = tid & 31;
    const int r = tid >> 5;                  // residue chain 0..8

    const size_t row = blockIdx.x;
    const float4* __restrict__ xr = (const float4*)(x + row * ROW_T);
    float4* __restrict__ outr = (float4*)(out + row * ROW_T);

    // x0 via global broadcast (no smem dependency on s[0])
    const float x0 = __ldg(x + row * ROW_T);

    // 1) coalesced stage, streaming loads
    #pragma unroll
    for (int q = tid; q < ROW_T / 4; q += NTHREADS) {
        ((float4*)s)[q] = __ldcs(xr + q);
    }
    __syncthreads();

    const int base = r + 135 * lane;         // lanes 0..29: base+126 <= 4049
    const int lim30 = (r == 0) ? 6 : 5;      // lane 30 valid count

    // 2) gather: lane l accumulates chain slots [15l, 15l+15) (lane-private)
    float a[PER_LANE];
    float run = 0.f;
    if (lane < 30) {
        #pragma unroll
        for (int j = 0; j < PER_LANE; j++) { run += s[base + 9 * j]; a[j] = run; }
    } else if (lane == 30) {
        #pragma unroll
        for (int j = 0; j < PER_LANE; j++) {
            if (j < lim30) run += s[base + 9 * j];
            a[j] = run;
        }
    }

    // 3) warp scan over lane totals -> exclusive carry (warp-synchronous)
    float incl = run;
    #pragma unroll
    for (int off = 1; off < 32; off <<= 1) {
        float up = __shfl_up_sync(0xffffffffu, incl, off);
        if (lane >= off) incl += up;
    }
    float e8 = 8.f * (incl - run);
    if (r <= 4) e8 -= 8.f * x0;              // fold x0 correction into S'

    // 4) writeback S' in place — same lane-private slots, no barrier needed
    if (lane < 30) {
        #pragma unroll
        for (int j = 0; j < PER_LANE; j++) s[base + 9 * j] = fmaf(8.f, a[j], e8);
    } else if (lane == 30) {
        #pragma unroll
        for (int j = 0; j < PER_LANE; j++)
            if (j < lim30) s[base + 9 * j] = fmaf(8.f, a[j], e8);
    }
    __syncthreads();

    // 5) diff pass: out[t] = S'[t] - S'[t-1], evict-first streaming stores
    #pragma unroll
    for (int q = tid; q < ROW_T / 4; q += NTHREADS) {
        float4 B = ((const float4*)s)[q];
        float prevw = __shfl_up_sync(0xffffffffu, B.w, 1);
        if (lane == 0) prevw = (q == 0) ? 0.f : s[4 * q - 1];
        float4 o;
        o.x = B.x - prevw;
        o.y = B.y - B.x;
        o.z = B.z - B.y;
        o.w = B.w - B.z;
        __stcs(outr + q, o);
    }
}

extern "C" void kernel_launch(void* const* d_in, const int* in_sizes, int n_in,
                              void* d_out, int out_size) {
    const float* x = (const float*)d_in[0];
    float* out = (float*)d_out;
    const int rows = in_sizes[0] / ROW_T;   // 16384
    inv_avgpool_kernel<<<rows, NTHREADS>>>(x, out);
}